// round 10
// baseline (speedup 1.0000x reference)
#include <cuda_runtime.h>
#include <cuda_bf16.h>
#include <cuda_fp16.h>
#include <math.h>
#include <stdint.h>

#define NMAX 30000
#define EMAX 480000
#define TEMAX (EMAX + NMAX)

// ------------------------- device scratch (static; no allocs) ----------------
__device__ __align__(16) __half g_hh[(size_t)NMAX * 512];   // GEMM output (fp16)
__device__ __align__(16) __nv_bfloat16 g_ah[(size_t)NMAX * 512];
__device__ __align__(16) __nv_bfloat16 g_al[(size_t)NMAX * 512];
__device__ __align__(16) __nv_bfloat16 g_wh[512 * 512];
__device__ __align__(16) __nv_bfloat16 g_wl[512 * 512];
__device__ __align__(16) float g_asrc[NMAX * 4];
__device__ __align__(16) float g_adst[NMAX * 4];
__device__ int   g_deg[NMAX];
__device__ int   g_off[NMAX + 1];
__device__ int   g_cur[NMAX];
__device__ int   g_esrc[TEMAX];

#define SW128(o) ((o) ^ (((o) >> 3) & 0x70))

__device__ __forceinline__ uint32_t smem_u32(const void* p) {
    uint32_t a;
    asm("{ .reg .u64 t; cvta.to.shared.u64 t, %1; cvt.u32.u64 %0, t; }" : "=r"(a) : "l"(p));
    return a;
}
__device__ __forceinline__ void ldm_x4(uint32_t* r, uint32_t addr) {
    asm volatile("ldmatrix.sync.aligned.m8n8.x4.shared.b16 {%0,%1,%2,%3}, [%4];"
                 : "=r"(r[0]), "=r"(r[1]), "=r"(r[2]), "=r"(r[3]) : "r"(addr));
}
__device__ __forceinline__ void mma16816(float* d, const uint32_t* a, const uint32_t* b) {
    asm volatile(
        "mma.sync.aligned.m16n8k16.row.col.f32.bf16.bf16.f32 "
        "{%0,%1,%2,%3}, {%4,%5,%6,%7}, {%8,%9}, {%0,%1,%2,%3};"
        : "+f"(d[0]), "+f"(d[1]), "+f"(d[2]), "+f"(d[3])
        : "r"(a[0]), "r"(a[1]), "r"(a[2]), "r"(a[3]), "r"(b[0]), "r"(b[1]));
}
__device__ __forceinline__ void cp_async16(uint32_t saddr, const void* g, int srcBytes) {
    asm volatile("cp.async.cg.shared.global [%0], [%1], 16, %2;"
                 :: "r"(saddr), "l"(g), "r"(srcBytes) : "memory");
}
#define CP_COMMIT() asm volatile("cp.async.commit_group;" ::: "memory")
#define CP_WAIT(n)  asm volatile("cp.async.wait_group %0;" :: "n"(n) : "memory")

// ------------------------- CSC build ----------------------------------------
__global__ void deg_init(int N) {
    int i = blockIdx.x * blockDim.x + threadIdx.x;
    if (i < N) g_deg[i] = 1;
}
__global__ void deg_count(const int* __restrict__ ei, int E, int N) {
    int i = blockIdx.x * blockDim.x + threadIdx.x;
    if (i < E) {
        int d = ei[E + i];
        if (d >= 0 && d < N) atomicAdd(&g_deg[d], 1);
    }
}
__global__ void scan1024(int N) {
    __shared__ int sp[1024];
    int t = threadIdx.x;
    int IT = (N + 1023) >> 10;
    int b = t * IT, e = min(N, b + IT);
    int s = 0;
    for (int i = b; i < e; i++) s += g_deg[i];
    sp[t] = s;
    __syncthreads();
    for (int off = 1; off < 1024; off <<= 1) {
        int v = (t >= off) ? sp[t - off] : 0;
        __syncthreads();
        sp[t] += v;
        __syncthreads();
    }
    int run = (t == 0) ? 0 : sp[t - 1];
    for (int i = b; i < e; i++) { g_off[i] = run; g_cur[i] = run; run += g_deg[i]; }
    if (t == 1023) g_off[N] = sp[1023];
}
__global__ void fill_csc(const int* __restrict__ ei, int E, int N) {
    int i = blockIdx.x * blockDim.x + threadIdx.x;
    if (i >= E + N) return;
    int s, d;
    if (i < E) { s = ei[i]; d = ei[E + i]; }
    else       { s = i - E; d = s; }
    if (s < 0 || s >= N || d < 0 || d >= N) return;
    int pos = atomicAdd(&g_cur[d], 1);
    if (pos >= 0 && pos < TEMAX) g_esrc[pos] = s;
}

// ------------------------- bf16 split (layer-1 input) / weight transpose -----
__global__ void split_bf16(const float* __restrict__ in, int n) {
    int i = blockIdx.x * blockDim.x + threadIdx.x;
    if (i >= n) return;
    float v = in[i];
    __nv_bfloat16 h = __float2bfloat16(v);
    g_ah[i] = h;
    g_al[i] = __float2bfloat16(v - __bfloat162float(h));
}
__global__ void wsplit(const float* __restrict__ W, int K, int N) {
    int i = blockIdx.x * blockDim.x + threadIdx.x;
    if (i >= K * N) return;
    int k = i / N, n = i - k * N;
    float v = W[i];
    __nv_bfloat16 h = __float2bfloat16(v);
    g_wh[(size_t)n * K + k] = h;
    g_wl[(size_t)n * K + k] = __float2bfloat16(v - __bfloat162float(h));
}

// ------------------------- HMMA bf16-split GEMM + fused attn -----------------
// CTA tile 256x128 (8 warps: 4M x 2N, warp tile 64x64). K-chunk 64.
// Stage: Ah(32K)|Al(32K)|Bh(16K)|Bl(16K) = 96KB, 2 stages.
#define STAGE_B 98304
#define OFF_AH 0
#define OFF_AL 32768
#define OFF_BH 65536
#define OFF_BL 81920
#define SMTOT (2 * STAGE_B)

__global__ __launch_bounds__(256) void hgemm(int M, int N, int K,
                                             const float* __restrict__ at_s,
                                             const float* __restrict__ at_d,
                                             int H) {
    extern __shared__ char smem[];
    uint32_t sb = smem_u32(smem);
    int t = threadIdx.x, lane = t & 31, wid = t >> 5;
    int wm = (wid & 3) * 64;        // warp M offset (0..192)
    int wn = (wid >> 2) * 64;       // warp N offset (0 or 64)
    int row0 = blockIdx.y * 256, col0 = blockIdx.x * 128;
    int hd = blockIdx.x;

    float acc[4][8][4];
#pragma unroll
    for (int i = 0; i < 4; i++)
#pragma unroll
        for (int j = 0; j < 8; j++)
#pragma unroll
            for (int k = 0; k < 4; k++) acc[i][j][k] = 0.f;

    int q = t & 7;    // 16B quad within 128B row
    int rr = t >> 3;  // 0..31
    int nc = K >> 6;

    auto issue = [&](int c) {
        int k0 = c << 6;
        uint32_t stg = sb + (uint32_t)(c & 1) * STAGE_B;
#pragma unroll
        for (int j = 0; j < 8; j++) {          // A: 256 rows
            int r = rr + j * 32;
            uint32_t off = SW128((uint32_t)(r * 128 + q * 16));
            int gr = row0 + r;
            int ok = (gr < M) ? 16 : 0;
            int grc = ok ? gr : 0;
            cp_async16(stg + OFF_AH + off, &g_ah[(size_t)grc * K + k0 + q * 8], ok);
            cp_async16(stg + OFF_AL + off, &g_al[(size_t)grc * K + k0 + q * 8], ok);
        }
#pragma unroll
        for (int j = 0; j < 4; j++) {          // B: 128 rows
            int r = rr + j * 32;
            uint32_t off = SW128((uint32_t)(r * 128 + q * 16));
            int gn = col0 + r;
            cp_async16(stg + OFF_BH + off, &g_wh[(size_t)gn * K + k0 + q * 8], 16);
            cp_async16(stg + OFF_BL + off, &g_wl[(size_t)gn * K + k0 + q * 8], 16);
        }
        CP_COMMIT();
    };

    issue(0);

    for (int c = 0; c < nc; c++) {
        if (c + 1 < nc) {
            issue(c + 1);
            CP_WAIT(1);
        } else {
            CP_WAIT(0);
        }
        __syncthreads();
        uint32_t stg = sb + (uint32_t)(c & 1) * STAGE_B;
#pragma unroll
        for (int ks = 0; ks < 4; ks++) {
            int kc = ks * 16;
            uint32_t ah[4][4], al[4][4];
#pragma unroll
            for (int mt = 0; mt < 4; mt++) {
                int r = wm + mt * 16 + (lane & 15);
                uint32_t off = SW128((uint32_t)(r * 128 + (kc + ((lane >> 4) << 3)) * 2));
                ldm_x4(ah[mt], stg + OFF_AH + off);
                ldm_x4(al[mt], stg + OFF_AL + off);
            }
            uint32_t bh[4][4], bl[4][4];
#pragma unroll
            for (int p = 0; p < 4; p++) {
                int r = wn + p * 16 + ((lane >> 4) << 3) + (lane & 7);
                uint32_t off = SW128((uint32_t)(r * 128 + (kc + ((lane >> 3) & 1) * 8) * 2));
                ldm_x4(bh[p], stg + OFF_BH + off);
                ldm_x4(bl[p], stg + OFF_BL + off);
            }
#pragma unroll
            for (int mt = 0; mt < 4; mt++)
#pragma unroll
                for (int nt = 0; nt < 8; nt++) {
                    const uint32_t* bph = &bh[nt >> 1][(nt & 1) * 2];
                    const uint32_t* bpl = &bl[nt >> 1][(nt & 1) * 2];
                    mma16816(acc[mt][nt], ah[mt], bph);
                    mma16816(acc[mt][nt], ah[mt], bpl);
                    mma16816(acc[mt][nt], al[mt], bph);
                }
        }
        __syncthreads();
    }

    // ---- epilogue: store h (fp16) ----
    int g = lane >> 2, cc = (lane & 3) * 2;
#pragma unroll
    for (int mt = 0; mt < 4; mt++) {
        int r0a = row0 + wm + mt * 16 + g;
#pragma unroll
        for (int nt = 0; nt < 8; nt++) {
            int c = col0 + wn + nt * 8 + cc;
            if (r0a < M)
                *(__half2*)&g_hh[(size_t)r0a * N + c] =
                    __floats2half2_rn(acc[mt][nt][0], acc[mt][nt][1]);
            if (r0a + 8 < M)
                *(__half2*)&g_hh[(size_t)(r0a + 8) * N + c] =
                    __floats2half2_rn(acc[mt][nt][2], acc[mt][nt][3]);
        }
    }

    // ---- fused attention coefficients for this head (from f32 acc) ----
    float ps[4][2], pd[4][2];
#pragma unroll
    for (int mt = 0; mt < 4; mt++) { ps[mt][0] = ps[mt][1] = pd[mt][0] = pd[mt][1] = 0.f; }
    const float* asv = at_s + hd * 128;
    const float* adv = at_d + hd * 128;
#pragma unroll
    for (int nt = 0; nt < 8; nt++) {
        int c = wn + nt * 8 + cc;
        float w0s = asv[c], w1s = asv[c + 1];
        float w0d = adv[c], w1d = adv[c + 1];
#pragma unroll
        for (int mt = 0; mt < 4; mt++) {
            ps[mt][0] += acc[mt][nt][0] * w0s + acc[mt][nt][1] * w1s;
            ps[mt][1] += acc[mt][nt][2] * w0s + acc[mt][nt][3] * w1s;
            pd[mt][0] += acc[mt][nt][0] * w0d + acc[mt][nt][1] * w1d;
            pd[mt][1] += acc[mt][nt][2] * w0d + acc[mt][nt][3] * w1d;
        }
    }
#pragma unroll
    for (int o = 1; o < 4; o <<= 1) {
#pragma unroll
        for (int mt = 0; mt < 4; mt++)
#pragma unroll
            for (int hf = 0; hf < 2; hf++) {
                ps[mt][hf] += __shfl_xor_sync(0xffffffffu, ps[mt][hf], o);
                pd[mt][hf] += __shfl_xor_sync(0xffffffffu, pd[mt][hf], o);
            }
    }
    // sred[half][row 0..255][2]
    float* sred = (float*)smem;
    __syncthreads();
    if ((lane & 3) == 0) {
#pragma unroll
        for (int mt = 0; mt < 4; mt++)
#pragma unroll
            for (int hf = 0; hf < 2; hf++) {
                int row = wm + mt * 16 + g + hf * 8;
                sred[(((wid >> 2) << 8) + row) * 2 + 0] = ps[mt][hf];
                sred[(((wid >> 2) << 8) + row) * 2 + 1] = pd[mt][hf];
            }
    }
    __syncthreads();
    {
        int gr = row0 + t;
        if (gr < M) {
            g_asrc[gr * H + hd] = sred[t * 2 + 0] + sred[(256 + t) * 2 + 0];
            g_adst[gr * H + hd] = sred[t * 2 + 1] + sred[(256 + t) * 2 + 1];
        }
    }
}

// ------------------------- fused softmax + aggregate + bf16 split ------------
// H=4: thread t owns channels [4t,4t+4) (head = t>>5). One LDG.64 (4 fp16)/edge.
__global__ void aggregate4(const float* __restrict__ bias, int doSplit,
                           float* __restrict__ outp) {
    int n = blockIdx.x;
    int t = threadIdx.x;
    int hd = t >> 5;
    __shared__ int   ssrc[128];
    __shared__ float sw[128 * 4];

    int beg = g_off[n], end = g_off[n + 1];

    float4 adh = *(const float4*)&g_adst[n * 4];
    float4 acc = make_float4(0.f, 0.f, 0.f, 0.f);
    float den = 0.f;

    for (int base = beg; base < end; base += 128) {
        int k = base + t;
        if (k < end) {
            int s = g_esrc[k];
            ssrc[t] = s;
            float4 a = *(const float4*)&g_asrc[s * 4];
            float e0 = a.x + adh.x, e1 = a.y + adh.y, e2 = a.z + adh.z, e3 = a.w + adh.w;
            e0 = e0 > 0.f ? e0 : 0.2f * e0;
            e1 = e1 > 0.f ? e1 : 0.2f * e1;
            e2 = e2 > 0.f ? e2 : 0.2f * e2;
            e3 = e3 > 0.f ? e3 : 0.2f * e3;
            *(float4*)&sw[t * 4] = make_float4(__expf(e0), __expf(e1), __expf(e2), __expf(e3));
        }
        __syncthreads();
        int cnt = min(128, end - base);
#pragma unroll 2
        for (int j = 0; j < cnt; j++) {
            int s = ssrc[j];
            float w = sw[j * 4 + hd];
            uint2 hv = *(const uint2*)&g_hh[(size_t)s * 512 + t * 4];
            float2 f01 = __half22float2(*(__half2*)&hv.x);
            float2 f23 = __half22float2(*(__half2*)&hv.y);
            acc.x += w * f01.x;
            acc.y += w * f01.y;
            acc.z += w * f23.x;
            acc.w += w * f23.y;
            den += w;
        }
        __syncthreads();
    }

    float inv = 1.f / den;
    float4 b4 = *(const float4*)&bias[t * 4];
    float v0 = fmaxf(acc.x * inv + b4.x, 0.f);
    float v1 = fmaxf(acc.y * inv + b4.y, 0.f);
    float v2 = fmaxf(acc.z * inv + b4.z, 0.f);
    float v3 = fmaxf(acc.w * inv + b4.w, 0.f);
    size_t idx = (size_t)n * 512 + t * 4;
    if (doSplit) {
        __nv_bfloat16 h0 = __float2bfloat16(v0), h1 = __float2bfloat16(v1);
        __nv_bfloat16 h2 = __float2bfloat16(v2), h3 = __float2bfloat16(v3);
        __nv_bfloat162 hi01, hi23;
        hi01.x = h0; hi01.y = h1; hi23.x = h2; hi23.y = h3;
        *(__nv_bfloat162*)&g_ah[idx] = hi01;
        *(__nv_bfloat162*)&g_ah[idx + 2] = hi23;
        __nv_bfloat162 lo01, lo23;
        lo01.x = __float2bfloat16(v0 - __bfloat162float(h0));
        lo01.y = __float2bfloat16(v1 - __bfloat162float(h1));
        lo23.x = __float2bfloat16(v2 - __bfloat162float(h2));
        lo23.y = __float2bfloat16(v3 - __bfloat162float(h3));
        *(__nv_bfloat162*)&g_al[idx] = lo01;
        *(__nv_bfloat162*)&g_al[idx + 2] = lo23;
    } else {
        outp[idx] = v0; outp[idx + 1] = v1; outp[idx + 2] = v2; outp[idx + 3] = v3;
    }
}

// H=1, C=128 (layer 3): thread t owns channel t, no relu.
__global__ void aggregate1(const float* __restrict__ bias, float* __restrict__ outp) {
    int n = blockIdx.x;
    int t = threadIdx.x;
    __shared__ int   ssrc[128];
    __shared__ float sw[128];

    int beg = g_off[n], end = g_off[n + 1];
    float adh = g_adst[n];
    float acc = 0.f, den = 0.f;

    for (int base = beg; base < end; base += 128) {
        int k = base + t;
        if (k < end) {
            int s = g_esrc[k];
            ssrc[t] = s;
            float e = g_asrc[s] + adh;
            e = e > 0.f ? e : 0.2f * e;
            sw[t] = __expf(e);
        }
        __syncthreads();
        int cnt = min(128, end - base);
#pragma unroll 2
        for (int j = 0; j < cnt; j++) {
            int s = ssrc[j];
            float w = sw[j];
            acc += w * __half2float(g_hh[(size_t)s * 128 + t]);
            den += w;
        }
        __syncthreads();
    }
    outp[(size_t)n * 128 + t] = acc / den + bias[t];
}

// ------------------------- launch ---------------------------------------------
extern "C" void kernel_launch(void* const* d_in, const int* in_sizes, int n_in,
                              void* d_out, int out_size) {
    const float* x   = (const float*)d_in[0];
    const int*   ei  = (const int*)d_in[1];
    const float* W1  = (const float*)d_in[2];
    const float* as1 = (const float*)d_in[3];
    const float* ad1 = (const float*)d_in[4];
    const float* b1  = (const float*)d_in[5];
    const float* W2  = (const float*)d_in[6];
    const float* as2 = (const float*)d_in[7];
    const float* ad2 = (const float*)d_in[8];
    const float* b2  = (const float*)d_in[9];
    const float* W3  = (const float*)d_in[10];
    const float* as3 = (const float*)d_in[11];
    const float* ad3 = (const float*)d_in[12];
    const float* b3  = (const float*)d_in[13];
    float* out = (float*)d_out;

    int N = in_sizes[0] / 256;   // 30000
    int E = in_sizes[1] / 2;     // 480000

    cudaFuncSetAttribute(hgemm, cudaFuncAttributeMaxDynamicSharedMemorySize, SMTOT);

    int MT = (N + 255) / 256;  // 118

    split_bf16<<<(N * 256 + 255) / 256, 256>>>(x, N * 256);            // 0
    wsplit<<<(256 * 512 + 255) / 256, 256>>>(W1, 256, 512);            // 1
    deg_init<<<(N + 255) / 256, 256>>>(N);                             // 2
    hgemm<<<dim3(4, MT), 256, SMTOT>>>(N, 512, 256, as1, ad1, 4);      // 3 <- captured
    deg_count<<<(E + 255) / 256, 256>>>(ei, E, N);                     // 4
    scan1024<<<1, 1024>>>(N);                                          // 5
    fill_csc<<<(E + N + 255) / 256, 256>>>(ei, E, N);                  // 6
    aggregate4<<<N, 128>>>(b1, 1, nullptr);                            // 7

    // ---- layer 2 ----
    wsplit<<<(512 * 512 + 255) / 256, 256>>>(W2, 512, 512);
    hgemm<<<dim3(4, MT), 256, SMTOT>>>(N, 512, 512, as2, ad2, 4);
    aggregate4<<<N, 128>>>(b2, 1, nullptr);

    // ---- layer 3 ----
    wsplit<<<(512 * 128 + 255) / 256, 256>>>(W3, 512, 128);
    hgemm<<<dim3(1, MT), 256, SMTOT>>>(N, 128, 512, as3, ad3, 1);
    aggregate1<<<N, 128>>>(b3, out);
}

// round 11
// speedup vs baseline: 1.1828x; 1.1828x over previous
#include <cuda_runtime.h>
#include <cuda_fp16.h>
#include <math.h>
#include <stdint.h>

#define NMAX 30000
#define EMAX 480000
#define TEMAX (EMAX + NMAX)

// ------------------------- device scratch (static; no allocs) ----------------
__device__ __align__(16) __half g_hh[(size_t)NMAX * 512];   // GEMM output (fp16)
__device__ __align__(16) __half g_ah[(size_t)NMAX * 512];   // activation hi (fp16)
__device__ __align__(16) __half g_al[(size_t)NMAX * 512];   // activation lo (fp16)
__device__ __align__(16) __half g_w[512 * 512];             // W^T (fp16)
__device__ __align__(16) float g_asrc[NMAX * 4];
__device__ __align__(16) float g_adst[NMAX * 4];
__device__ int   g_deg[NMAX];
__device__ int   g_off[NMAX + 1];
__device__ int   g_cur[NMAX];
__device__ int   g_esrc[TEMAX];

#define SW128(o) ((o) ^ (((o) >> 3) & 0x70))

__device__ __forceinline__ uint32_t smem_u32(const void* p) {
    uint32_t a;
    asm("{ .reg .u64 t; cvta.to.shared.u64 t, %1; cvt.u32.u64 %0, t; }" : "=r"(a) : "l"(p));
    return a;
}
__device__ __forceinline__ void ldm_x4(uint32_t* r, uint32_t addr) {
    asm volatile("ldmatrix.sync.aligned.m8n8.x4.shared.b16 {%0,%1,%2,%3}, [%4];"
                 : "=r"(r[0]), "=r"(r[1]), "=r"(r[2]), "=r"(r[3]) : "r"(addr));
}
__device__ __forceinline__ void mma16816(float* d, const uint32_t* a, const uint32_t* b) {
    asm volatile(
        "mma.sync.aligned.m16n8k16.row.col.f32.f16.f16.f32 "
        "{%0,%1,%2,%3}, {%4,%5,%6,%7}, {%8,%9}, {%0,%1,%2,%3};"
        : "+f"(d[0]), "+f"(d[1]), "+f"(d[2]), "+f"(d[3])
        : "r"(a[0]), "r"(a[1]), "r"(a[2]), "r"(a[3]), "r"(b[0]), "r"(b[1]));
}
__device__ __forceinline__ void cp_async16(uint32_t saddr, const void* g, int srcBytes) {
    asm volatile("cp.async.cg.shared.global [%0], [%1], 16, %2;"
                 :: "r"(saddr), "l"(g), "r"(srcBytes) : "memory");
}
#define CP_COMMIT() asm volatile("cp.async.commit_group;" ::: "memory")
#define CP_WAIT(n)  asm volatile("cp.async.wait_group %0;" :: "n"(n) : "memory")

// ------------------------- CSC build ----------------------------------------
__global__ void deg_init(int N) {
    int i = blockIdx.x * blockDim.x + threadIdx.x;
    if (i < N) g_deg[i] = 1;
}
__global__ void deg_count(const int* __restrict__ ei, int E, int N) {
    int i = blockIdx.x * blockDim.x + threadIdx.x;
    if (i < E) {
        int d = ei[E + i];
        if (d >= 0 && d < N) atomicAdd(&g_deg[d], 1);
    }
}
__global__ void scan1024(int N) {
    __shared__ int sp[1024];
    int t = threadIdx.x;
    int IT = (N + 1023) >> 10;
    int b = t * IT, e = min(N, b + IT);
    int s = 0;
    for (int i = b; i < e; i++) s += g_deg[i];
    sp[t] = s;
    __syncthreads();
    for (int off = 1; off < 1024; off <<= 1) {
        int v = (t >= off) ? sp[t - off] : 0;
        __syncthreads();
        sp[t] += v;
        __syncthreads();
    }
    int run = (t == 0) ? 0 : sp[t - 1];
    for (int i = b; i < e; i++) { g_off[i] = run; g_cur[i] = run; run += g_deg[i]; }
    if (t == 1023) g_off[N] = sp[1023];
}
__global__ void fill_csc(const int* __restrict__ ei, int E, int N) {
    int i = blockIdx.x * blockDim.x + threadIdx.x;
    if (i >= E + N) return;
    int s, d;
    if (i < E) { s = ei[i]; d = ei[E + i]; }
    else       { s = i - E; d = s; }
    if (s < 0 || s >= N || d < 0 || d >= N) return;
    int pos = atomicAdd(&g_cur[d], 1);
    if (pos >= 0 && pos < TEMAX) g_esrc[pos] = s;
}

// ------------------------- fp16 split (layer-1 input) / weight transpose -----
__global__ void split_fp16(const float* __restrict__ in, int n) {
    int i = blockIdx.x * blockDim.x + threadIdx.x;
    if (i >= n) return;
    float v = in[i];
    __half h = __float2half_rn(v);
    g_ah[i] = h;
    g_al[i] = __float2half_rn(v - __half2float(h));
}
__global__ void wsplit(const float* __restrict__ W, int K, int N) {
    int i = blockIdx.x * blockDim.x + threadIdx.x;
    if (i >= K * N) return;
    int k = i / N, n = i - k * N;
    g_w[(size_t)n * K + k] = __float2half_rn(W[i]);
}

// ------------------------- HMMA fp16 2-term GEMM + fused attn ----------------
// C[M,N] = A·W, A = g_ah+g_al [M,K], Wt = g_w [N,K]. D = Ah·B + Al·B.
// CTA tile 128x128 (8 warps: 4M x 2N, warp tile 32x64). K-chunk 64.
// Stage: Ah|Al|B @16KB = 48KB, 3 stages = 144KB.
#define STAGE_B 49152
#define OFF_AH 0
#define OFF_AL 16384
#define OFF_B  32768
#define SMTOT (3 * STAGE_B)

__global__ __launch_bounds__(256) void hgemm(int M, int N, int K,
                                             const float* __restrict__ at_s,
                                             const float* __restrict__ at_d,
                                             int H) {
    extern __shared__ char smem[];
    uint32_t sb = smem_u32(smem);
    int t = threadIdx.x, lane = t & 31, wid = t >> 5;
    int wm = (wid & 3) * 32;
    int wn = (wid >> 2) * 64;
    int row0 = blockIdx.y * 128, col0 = blockIdx.x * 128;
    int hd = blockIdx.x;

    float acc[2][8][4];
#pragma unroll
    for (int i = 0; i < 2; i++)
#pragma unroll
        for (int j = 0; j < 8; j++)
#pragma unroll
            for (int k = 0; k < 4; k++) acc[i][j][k] = 0.f;

    int q = t & 7;
    int rr = t >> 3;
    int nc = K >> 6;

    auto issue = [&](int c) {
        int k0 = c << 6;
        uint32_t stg = sb + (uint32_t)(c % 3) * STAGE_B;
#pragma unroll
        for (int j = 0; j < 4; j++) {
            int r = rr + j * 32;
            uint32_t off = SW128((uint32_t)(r * 128 + q * 16));
            int gr = row0 + r;
            int ok = (gr < M) ? 16 : 0;
            int grc = ok ? gr : 0;
            cp_async16(stg + OFF_AH + off, &g_ah[(size_t)grc * K + k0 + q * 8], ok);
            cp_async16(stg + OFF_AL + off, &g_al[(size_t)grc * K + k0 + q * 8], ok);
            int gn = col0 + r;
            cp_async16(stg + OFF_B + off, &g_w[(size_t)gn * K + k0 + q * 8], 16);
        }
        CP_COMMIT();
    };

    issue(0);
    if (nc > 1) issue(1);

    for (int c = 0; c < nc; c++) {
        if (c + 2 < nc) {
            issue(c + 2);
            CP_WAIT(2);
        } else if (c + 1 < nc) {
            CP_WAIT(1);
        } else {
            CP_WAIT(0);
        }
        __syncthreads();
        uint32_t stg = sb + (uint32_t)(c % 3) * STAGE_B;
#pragma unroll
        for (int ks = 0; ks < 4; ks++) {
            int kc = ks * 16;
            uint32_t ah[2][4], al[2][4];
#pragma unroll
            for (int mt = 0; mt < 2; mt++) {
                int r = wm + mt * 16 + (lane & 15);
                uint32_t off = SW128((uint32_t)(r * 128 + (kc + ((lane >> 4) << 3)) * 2));
                ldm_x4(ah[mt], stg + OFF_AH + off);
                ldm_x4(al[mt], stg + OFF_AL + off);
            }
            uint32_t bb[4][4];
#pragma unroll
            for (int p = 0; p < 4; p++) {
                int r = wn + p * 16 + ((lane >> 4) << 3) + (lane & 7);
                uint32_t off = SW128((uint32_t)(r * 128 + (kc + ((lane >> 3) & 1) * 8) * 2));
                ldm_x4(bb[p], stg + OFF_B + off);
            }
#pragma unroll
            for (int mt = 0; mt < 2; mt++)
#pragma unroll
                for (int nt = 0; nt < 8; nt++) {
                    const uint32_t* bp = &bb[nt >> 1][(nt & 1) * 2];
                    mma16816(acc[mt][nt], ah[mt], bp);
                    mma16816(acc[mt][nt], al[mt], bp);
                }
        }
        __syncthreads();
    }

    // ---- epilogue: store h (fp16) ----
    int g = lane >> 2, cc = (lane & 3) * 2;
#pragma unroll
    for (int mt = 0; mt < 2; mt++) {
        int r0a = row0 + wm + mt * 16 + g;
#pragma unroll
        for (int nt = 0; nt < 8; nt++) {
            int c = col0 + wn + nt * 8 + cc;
            if (r0a < M)
                *(__half2*)&g_hh[(size_t)r0a * N + c] =
                    __floats2half2_rn(acc[mt][nt][0], acc[mt][nt][1]);
            if (r0a + 8 < M)
                *(__half2*)&g_hh[(size_t)(r0a + 8) * N + c] =
                    __floats2half2_rn(acc[mt][nt][2], acc[mt][nt][3]);
        }
    }

    // ---- fused attention coefficients for this head (from f32 acc) ----
    float ps[2][2] = {{0.f, 0.f}, {0.f, 0.f}};
    float pd[2][2] = {{0.f, 0.f}, {0.f, 0.f}};
    const float* asv = at_s + hd * 128;
    const float* adv = at_d + hd * 128;
#pragma unroll
    for (int nt = 0; nt < 8; nt++) {
        int c = wn + nt * 8 + cc;
        float w0s = asv[c], w1s = asv[c + 1];
        float w0d = adv[c], w1d = adv[c + 1];
#pragma unroll
        for (int mt = 0; mt < 2; mt++) {
            ps[mt][0] += acc[mt][nt][0] * w0s + acc[mt][nt][1] * w1s;
            ps[mt][1] += acc[mt][nt][2] * w0s + acc[mt][nt][3] * w1s;
            pd[mt][0] += acc[mt][nt][0] * w0d + acc[mt][nt][1] * w1d;
            pd[mt][1] += acc[mt][nt][2] * w0d + acc[mt][nt][3] * w1d;
        }
    }
#pragma unroll
    for (int o = 1; o < 4; o <<= 1) {
#pragma unroll
        for (int mt = 0; mt < 2; mt++)
#pragma unroll
            for (int hf = 0; hf < 2; hf++) {
                ps[mt][hf] += __shfl_xor_sync(0xffffffffu, ps[mt][hf], o);
                pd[mt][hf] += __shfl_xor_sync(0xffffffffu, pd[mt][hf], o);
            }
    }
    float* sred = (float*)smem;
    __syncthreads();
    if ((lane & 3) == 0) {
#pragma unroll
        for (int mt = 0; mt < 2; mt++)
#pragma unroll
            for (int hf = 0; hf < 2; hf++) {
                int row = wm + mt * 16 + g + hf * 8;
                sred[((wid >> 2) * 128 + row) * 2 + 0] = ps[mt][hf];
                sred[((wid >> 2) * 128 + row) * 2 + 1] = pd[mt][hf];
            }
    }
    __syncthreads();
    if (t < 128) {
        int gr = row0 + t;
        if (gr < M) {
            g_asrc[gr * H + hd] = sred[t * 2 + 0] + sred[(128 + t) * 2 + 0];
            g_adst[gr * H + hd] = sred[t * 2 + 1] + sred[(128 + t) * 2 + 1];
        }
    }
}

// ------------------------- fused softmax + aggregate + fp16 split ------------
// H=4: thread t owns channels [4t,4t+4) (head = t>>5). One LDG.64 (4 fp16)/edge.
__global__ void aggregate4(const float* __restrict__ bias, int doSplit,
                           float* __restrict__ outp) {
    int n = blockIdx.x;
    int t = threadIdx.x;
    int hd = t >> 5;
    __shared__ int   ssrc[128];
    __shared__ float sw[128 * 4];

    int beg = g_off[n], end = g_off[n + 1];

    float4 adh = *(const float4*)&g_adst[n * 4];
    float4 acc = make_float4(0.f, 0.f, 0.f, 0.f);
    float den = 0.f;

    for (int base = beg; base < end; base += 128) {
        int k = base + t;
        if (k < end) {
            int s = g_esrc[k];
            ssrc[t] = s;
            float4 a = *(const float4*)&g_asrc[s * 4];
            float e0 = a.x + adh.x, e1 = a.y + adh.y, e2 = a.z + adh.z, e3 = a.w + adh.w;
            e0 = e0 > 0.f ? e0 : 0.2f * e0;
            e1 = e1 > 0.f ? e1 : 0.2f * e1;
            e2 = e2 > 0.f ? e2 : 0.2f * e2;
            e3 = e3 > 0.f ? e3 : 0.2f * e3;
            *(float4*)&sw[t * 4] = make_float4(__expf(e0), __expf(e1), __expf(e2), __expf(e3));
        }
        __syncthreads();
        int cnt = min(128, end - base);
#pragma unroll 2
        for (int j = 0; j < cnt; j++) {
            int s = ssrc[j];
            float w = sw[j * 4 + hd];
            uint2 hv = *(const uint2*)&g_hh[(size_t)s * 512 + t * 4];
            float2 f01 = __half22float2(*(__half2*)&hv.x);
            float2 f23 = __half22float2(*(__half2*)&hv.y);
            acc.x += w * f01.x;
            acc.y += w * f01.y;
            acc.z += w * f23.x;
            acc.w += w * f23.y;
            den += w;
        }
        __syncthreads();
    }

    float inv = 1.f / den;
    float4 b4 = *(const float4*)&bias[t * 4];
    float v0 = fmaxf(acc.x * inv + b4.x, 0.f);
    float v1 = fmaxf(acc.y * inv + b4.y, 0.f);
    float v2 = fmaxf(acc.z * inv + b4.z, 0.f);
    float v3 = fmaxf(acc.w * inv + b4.w, 0.f);
    size_t idx = (size_t)n * 512 + t * 4;
    if (doSplit) {
        __half h0 = __float2half_rn(v0), h1 = __float2half_rn(v1);
        __half h2 = __float2half_rn(v2), h3 = __float2half_rn(v3);
        __half2 hi01, hi23, lo01, lo23;
        hi01.x = h0; hi01.y = h1; hi23.x = h2; hi23.y = h3;
        lo01.x = __float2half_rn(v0 - __half2float(h0));
        lo01.y = __float2half_rn(v1 - __half2float(h1));
        lo23.x = __float2half_rn(v2 - __half2float(h2));
        lo23.y = __float2half_rn(v3 - __half2float(h3));
        *(__half2*)&g_ah[idx] = hi01;
        *(__half2*)&g_ah[idx + 2] = hi23;
        *(__half2*)&g_al[idx] = lo01;
        *(__half2*)&g_al[idx + 2] = lo23;
    } else {
        outp[idx] = v0; outp[idx + 1] = v1; outp[idx + 2] = v2; outp[idx + 3] = v3;
    }
}

// H=1, C=128 (layer 3): thread t owns channel t, no relu.
__global__ void aggregate1(const float* __restrict__ bias, float* __restrict__ outp) {
    int n = blockIdx.x;
    int t = threadIdx.x;
    __shared__ int   ssrc[128];
    __shared__ float sw[128];

    int beg = g_off[n], end = g_off[n + 1];
    float adh = g_adst[n];
    float acc = 0.f, den = 0.f;

    for (int base = beg; base < end; base += 128) {
        int k = base + t;
        if (k < end) {
            int s = g_esrc[k];
            ssrc[t] = s;
            float e = g_asrc[s] + adh;
            e = e > 0.f ? e : 0.2f * e;
            sw[t] = __expf(e);
        }
        __syncthreads();
        int cnt = min(128, end - base);
#pragma unroll 2
        for (int j = 0; j < cnt; j++) {
            int s = ssrc[j];
            float w = sw[j];
            acc += w * __half2float(g_hh[(size_t)s * 128 + t]);
            den += w;
        }
        __syncthreads();
    }
    outp[(size_t)n * 128 + t] = acc / den + bias[t];
}

// ------------------------- launch ---------------------------------------------
extern "C" void kernel_launch(void* const* d_in, const int* in_sizes, int n_in,
                              void* d_out, int out_size) {
    const float* x   = (const float*)d_in[0];
    const int*   ei  = (const int*)d_in[1];
    const float* W1  = (const float*)d_in[2];
    const float* as1 = (const float*)d_in[3];
    const float* ad1 = (const float*)d_in[4];
    const float* b1  = (const float*)d_in[5];
    const float* W2  = (const float*)d_in[6];
    const float* as2 = (const float*)d_in[7];
    const float* ad2 = (const float*)d_in[8];
    const float* b2  = (const float*)d_in[9];
    const float* W3  = (const float*)d_in[10];
    const float* as3 = (const float*)d_in[11];
    const float* ad3 = (const float*)d_in[12];
    const float* b3  = (const float*)d_in[13];
    float* out = (float*)d_out;

    int N = in_sizes[0] / 256;   // 30000
    int E = in_sizes[1] / 2;     // 480000

    cudaFuncSetAttribute(hgemm, cudaFuncAttributeMaxDynamicSharedMemorySize, SMTOT);

    int MT = (N + 127) / 128;  // 235

    split_fp16<<<(N * 256 + 255) / 256, 256>>>(x, N * 256);            // 0
    wsplit<<<(256 * 512 + 255) / 256, 256>>>(W1, 256, 512);            // 1
    deg_init<<<(N + 255) / 256, 256>>>(N);                             // 2
    hgemm<<<dim3(4, MT), 256, SMTOT>>>(N, 512, 256, as1, ad1, 4);      // 3 <- captured
    deg_count<<<(E + 255) / 256, 256>>>(ei, E, N);                     // 4
    scan1024<<<1, 1024>>>(N);                                          // 5
    fill_csc<<<(E + N + 255) / 256, 256>>>(ei, E, N);                  // 6
    aggregate4<<<N, 128>>>(b1, 1, nullptr);                            // 7

    // ---- layer 2 ----
    wsplit<<<(512 * 512 + 255) / 256, 256>>>(W2, 512, 512);
    hgemm<<<dim3(4, MT), 256, SMTOT>>>(N, 512, 512, as2, ad2, 4);
    aggregate4<<<N, 128>>>(b2, 1, nullptr);

    // ---- layer 3 ----
    wsplit<<<(512 * 128 + 255) / 256, 256>>>(W3, 512, 128);
    hgemm<<<dim3(1, MT), 256, SMTOT>>>(N, 128, 512, as3, ad3, 1);
    aggregate1<<<N, 128>>>(b3, out);
}

// round 12
// speedup vs baseline: 1.2432x; 1.0511x over previous
#include <cuda_runtime.h>
#include <cuda_fp16.h>
#include <math.h>
#include <stdint.h>

#define NMAX 30000
#define EMAX 480000
#define TEMAX (EMAX + NMAX)

// ------------------------- device scratch (static; no allocs) ----------------
__device__ __align__(16) __half g_hh[(size_t)NMAX * 512];   // GEMM output (fp16)
__device__ __align__(16) __half g_ah[(size_t)NMAX * 512];   // activation hi (fp16)
__device__ __align__(16) __half g_al[(size_t)NMAX * 512];   // activation lo (fp16)
__device__ __align__(16) __half g_w[512 * 512];             // W^T (fp16)
__device__ __align__(16) float g_asrc[NMAX * 4];
__device__ __align__(16) float g_adst[NMAX * 4];
__device__ int   g_deg[NMAX];
__device__ int   g_off[NMAX + 1];
__device__ int   g_cur[NMAX];
__device__ int   g_esrc[TEMAX];

#define SW128(o) ((o) ^ (((o) >> 3) & 0x70))

__device__ __forceinline__ uint32_t smem_u32(const void* p) {
    uint32_t a;
    asm("{ .reg .u64 t; cvta.to.shared.u64 t, %1; cvt.u32.u64 %0, t; }" : "=r"(a) : "l"(p));
    return a;
}
__device__ __forceinline__ void ldm_x4(uint32_t* r, uint32_t addr) {
    asm volatile("ldmatrix.sync.aligned.m8n8.x4.shared.b16 {%0,%1,%2,%3}, [%4];"
                 : "=r"(r[0]), "=r"(r[1]), "=r"(r[2]), "=r"(r[3]) : "r"(addr));
}
__device__ __forceinline__ void mma16816(float* d, const uint32_t* a, const uint32_t* b) {
    asm volatile(
        "mma.sync.aligned.m16n8k16.row.col.f32.f16.f16.f32 "
        "{%0,%1,%2,%3}, {%4,%5,%6,%7}, {%8,%9}, {%0,%1,%2,%3};"
        : "+f"(d[0]), "+f"(d[1]), "+f"(d[2]), "+f"(d[3])
        : "r"(a[0]), "r"(a[1]), "r"(a[2]), "r"(a[3]), "r"(b[0]), "r"(b[1]));
}
__device__ __forceinline__ void cp_async16(uint32_t saddr, const void* g, int srcBytes) {
    asm volatile("cp.async.cg.shared.global [%0], [%1], 16, %2;"
                 :: "r"(saddr), "l"(g), "r"(srcBytes) : "memory");
}
#define CP_COMMIT() asm volatile("cp.async.commit_group;" ::: "memory")
#define CP_WAIT(n)  asm volatile("cp.async.wait_group %0;" :: "n"(n) : "memory")

// ------------------------- CSC build ----------------------------------------
__global__ void deg_init(int N) {
    int i = blockIdx.x * blockDim.x + threadIdx.x;
    if (i < N) g_deg[i] = 1;
}
__global__ void deg_count(const int* __restrict__ ei, int E, int N) {
    int i = blockIdx.x * blockDim.x + threadIdx.x;
    if (i < E) {
        int d = ei[E + i];
        if (d >= 0 && d < N) atomicAdd(&g_deg[d], 1);
    }
}
__global__ void scan1024(int N) {
    __shared__ int sp[1024];
    int t = threadIdx.x;
    int IT = (N + 1023) >> 10;
    int b = t * IT, e = min(N, b + IT);
    int s = 0;
    for (int i = b; i < e; i++) s += g_deg[i];
    sp[t] = s;
    __syncthreads();
    for (int off = 1; off < 1024; off <<= 1) {
        int v = (t >= off) ? sp[t - off] : 0;
        __syncthreads();
        sp[t] += v;
        __syncthreads();
    }
    int run = (t == 0) ? 0 : sp[t - 1];
    for (int i = b; i < e; i++) { g_off[i] = run; g_cur[i] = run; run += g_deg[i]; }
    if (t == 1023) g_off[N] = sp[1023];
}
__global__ void fill_csc(const int* __restrict__ ei, int E, int N) {
    int i = blockIdx.x * blockDim.x + threadIdx.x;
    if (i >= E + N) return;
    int s, d;
    if (i < E) { s = ei[i]; d = ei[E + i]; }
    else       { s = i - E; d = s; }
    if (s < 0 || s >= N || d < 0 || d >= N) return;
    int pos = atomicAdd(&g_cur[d], 1);
    if (pos >= 0 && pos < TEMAX) g_esrc[pos] = s;
}

// ------------------------- fp16 split (layer-1 input) / weight transpose -----
__global__ void split_fp16(const float* __restrict__ in, int n) {
    int i = blockIdx.x * blockDim.x + threadIdx.x;
    if (i >= n) return;
    float v = in[i];
    __half h = __float2half_rn(v);
    g_ah[i] = h;
    g_al[i] = __float2half_rn(v - __half2float(h));
}
__global__ void wsplit(const float* __restrict__ W, int K, int N) {
    int i = blockIdx.x * blockDim.x + threadIdx.x;
    if (i >= K * N) return;
    int k = i / N, n = i - k * N;
    g_w[(size_t)n * K + k] = __float2half_rn(W[i]);
}

// ------------------------- HMMA fp16 2-term GEMM + fused attn ----------------
// C[M,N] = A·W, A = g_ah+g_al [M,K], Wt = g_w [N,K]. D = Ah·B + Al·B.
// CTA tile 128x128 (8 warps: 4M x 2N). K-chunk 64. 2 stages @48KB = 96KB.
// __launch_bounds__(256,2): 2 CTAs/SM for barrier/latency hiding.
#define STAGE_B 49152
#define OFF_AH 0
#define OFF_AL 16384
#define OFF_B  32768
#define SMTOT (2 * STAGE_B)

__global__ __launch_bounds__(256, 2) void hgemm(int M, int N, int K,
                                                const float* __restrict__ at_s,
                                                const float* __restrict__ at_d,
                                                int H) {
    extern __shared__ char smem[];
    uint32_t sb = smem_u32(smem);
    int t = threadIdx.x, lane = t & 31, wid = t >> 5;
    int wm = (wid & 3) * 32;
    int wn = (wid >> 2) * 64;
    int row0 = blockIdx.y * 128, col0 = blockIdx.x * 128;
    int hd = blockIdx.x;

    float acc[2][8][4];
#pragma unroll
    for (int i = 0; i < 2; i++)
#pragma unroll
        for (int j = 0; j < 8; j++)
#pragma unroll
            for (int k = 0; k < 4; k++) acc[i][j][k] = 0.f;

    int q = t & 7;
    int rr = t >> 3;
    int nc = K >> 6;

    auto issue = [&](int c) {
        int k0 = c << 6;
        uint32_t stg = sb + (uint32_t)(c & 1) * STAGE_B;
#pragma unroll
        for (int j = 0; j < 4; j++) {
            int r = rr + j * 32;
            uint32_t off = SW128((uint32_t)(r * 128 + q * 16));
            int gr = row0 + r;
            int ok = (gr < M) ? 16 : 0;
            int grc = ok ? gr : 0;
            cp_async16(stg + OFF_AH + off, &g_ah[(size_t)grc * K + k0 + q * 8], ok);
            cp_async16(stg + OFF_AL + off, &g_al[(size_t)grc * K + k0 + q * 8], ok);
            int gn = col0 + r;
            cp_async16(stg + OFF_B + off, &g_w[(size_t)gn * K + k0 + q * 8], 16);
        }
        CP_COMMIT();
    };

    issue(0);

    for (int c = 0; c < nc; c++) {
        if (c + 1 < nc) {
            issue(c + 1);
            CP_WAIT(1);
        } else {
            CP_WAIT(0);
        }
        __syncthreads();
        uint32_t stg = sb + (uint32_t)(c & 1) * STAGE_B;
#pragma unroll
        for (int ks = 0; ks < 4; ks++) {
            int kc = ks * 16;
            uint32_t ah[2][4], al[2][4];
#pragma unroll
            for (int mt = 0; mt < 2; mt++) {
                int r = wm + mt * 16 + (lane & 15);
                uint32_t off = SW128((uint32_t)(r * 128 + (kc + ((lane >> 4) << 3)) * 2));
                ldm_x4(ah[mt], stg + OFF_AH + off);
                ldm_x4(al[mt], stg + OFF_AL + off);
            }
            uint32_t bb[4][4];
#pragma unroll
            for (int p = 0; p < 4; p++) {
                int r = wn + p * 16 + ((lane >> 4) << 3) + (lane & 7);
                uint32_t off = SW128((uint32_t)(r * 128 + (kc + ((lane >> 3) & 1) * 8) * 2));
                ldm_x4(bb[p], stg + OFF_B + off);
            }
#pragma unroll
            for (int mt = 0; mt < 2; mt++)
#pragma unroll
                for (int nt = 0; nt < 8; nt++) {
                    const uint32_t* bp = &bb[nt >> 1][(nt & 1) * 2];
                    mma16816(acc[mt][nt], ah[mt], bp);
                    mma16816(acc[mt][nt], al[mt], bp);
                }
        }
        __syncthreads();
    }

    // ---- epilogue: store h (fp16) ----
    int g = lane >> 2, cc = (lane & 3) * 2;
#pragma unroll
    for (int mt = 0; mt < 2; mt++) {
        int r0a = row0 + wm + mt * 16 + g;
#pragma unroll
        for (int nt = 0; nt < 8; nt++) {
            int c = col0 + wn + nt * 8 + cc;
            if (r0a < M)
                *(__half2*)&g_hh[(size_t)r0a * N + c] =
                    __floats2half2_rn(acc[mt][nt][0], acc[mt][nt][1]);
            if (r0a + 8 < M)
                *(__half2*)&g_hh[(size_t)(r0a + 8) * N + c] =
                    __floats2half2_rn(acc[mt][nt][2], acc[mt][nt][3]);
        }
    }

    // ---- fused attention coefficients for this head (from f32 acc) ----
    float ps[2][2] = {{0.f, 0.f}, {0.f, 0.f}};
    float pd[2][2] = {{0.f, 0.f}, {0.f, 0.f}};
    const float* asv = at_s + hd * 128;
    const float* adv = at_d + hd * 128;
#pragma unroll
    for (int nt = 0; nt < 8; nt++) {
        int c = wn + nt * 8 + cc;
        float w0s = asv[c], w1s = asv[c + 1];
        float w0d = adv[c], w1d = adv[c + 1];
#pragma unroll
        for (int mt = 0; mt < 2; mt++) {
            ps[mt][0] += acc[mt][nt][0] * w0s + acc[mt][nt][1] * w1s;
            ps[mt][1] += acc[mt][nt][2] * w0s + acc[mt][nt][3] * w1s;
            pd[mt][0] += acc[mt][nt][0] * w0d + acc[mt][nt][1] * w1d;
            pd[mt][1] += acc[mt][nt][2] * w0d + acc[mt][nt][3] * w1d;
        }
    }
#pragma unroll
    for (int o = 1; o < 4; o <<= 1) {
#pragma unroll
        for (int mt = 0; mt < 2; mt++)
#pragma unroll
            for (int hf = 0; hf < 2; hf++) {
                ps[mt][hf] += __shfl_xor_sync(0xffffffffu, ps[mt][hf], o);
                pd[mt][hf] += __shfl_xor_sync(0xffffffffu, pd[mt][hf], o);
            }
    }
    float* sred = (float*)smem;
    __syncthreads();
    if ((lane & 3) == 0) {
#pragma unroll
        for (int mt = 0; mt < 2; mt++)
#pragma unroll
            for (int hf = 0; hf < 2; hf++) {
                int row = wm + mt * 16 + g + hf * 8;
                sred[((wid >> 2) * 128 + row) * 2 + 0] = ps[mt][hf];
                sred[((wid >> 2) * 128 + row) * 2 + 1] = pd[mt][hf];
            }
    }
    __syncthreads();
    if (t < 128) {
        int gr = row0 + t;
        if (gr < M) {
            g_asrc[gr * H + hd] = sred[t * 2 + 0] + sred[(128 + t) * 2 + 0];
            g_adst[gr * H + hd] = sred[t * 2 + 1] + sred[(128 + t) * 2 + 1];
        }
    }
}

// ------------------------- fused softmax + aggregate + fp16 split ------------
// H=4: thread t owns channels [4t,4t+4) (head = t>>5). One LDG.64 (4 fp16)/edge.
__global__ void aggregate4(const float* __restrict__ bias, int doSplit,
                           float* __restrict__ outp) {
    int n = blockIdx.x;
    int t = threadIdx.x;
    int hd = t >> 5;
    __shared__ int   ssrc[128];
    __shared__ float sw[128 * 4];

    int beg = g_off[n], end = g_off[n + 1];

    float4 adh = *(const float4*)&g_adst[n * 4];
    float4 acc = make_float4(0.f, 0.f, 0.f, 0.f);
    float den = 0.f;

    for (int base = beg; base < end; base += 128) {
        int k = base + t;
        if (k < end) {
            int s = g_esrc[k];
            ssrc[t] = s;
            float4 a = *(const float4*)&g_asrc[s * 4];
            float e0 = a.x + adh.x, e1 = a.y + adh.y, e2 = a.z + adh.z, e3 = a.w + adh.w;
            e0 = e0 > 0.f ? e0 : 0.2f * e0;
            e1 = e1 > 0.f ? e1 : 0.2f * e1;
            e2 = e2 > 0.f ? e2 : 0.2f * e2;
            e3 = e3 > 0.f ? e3 : 0.2f * e3;
            *(float4*)&sw[t * 4] = make_float4(__expf(e0), __expf(e1), __expf(e2), __expf(e3));
        }
        __syncthreads();
        int cnt = min(128, end - base);
        const __half* hbase = g_hh + t * 4;
#pragma unroll 4
        for (int j = 0; j < cnt; j++) {
            int s = ssrc[j];
            float w = sw[j * 4 + hd];
            uint2 hv = *(const uint2*)(hbase + (size_t)s * 512);
            float2 f01 = __half22float2(*(__half2*)&hv.x);
            float2 f23 = __half22float2(*(__half2*)&hv.y);
            acc.x += w * f01.x;
            acc.y += w * f01.y;
            acc.z += w * f23.x;
            acc.w += w * f23.y;
            den += w;
        }
        __syncthreads();
    }

    float inv = 1.f / den;
    float4 b4 = *(const float4*)&bias[t * 4];
    float v0 = fmaxf(acc.x * inv + b4.x, 0.f);
    float v1 = fmaxf(acc.y * inv + b4.y, 0.f);
    float v2 = fmaxf(acc.z * inv + b4.z, 0.f);
    float v3 = fmaxf(acc.w * inv + b4.w, 0.f);
    size_t idx = (size_t)n * 512 + t * 4;
    if (doSplit) {
        __half h0 = __float2half_rn(v0), h1 = __float2half_rn(v1);
        __half h2 = __float2half_rn(v2), h3 = __float2half_rn(v3);
        __half2 hi01, hi23, lo01, lo23;
        hi01.x = h0; hi01.y = h1; hi23.x = h2; hi23.y = h3;
        lo01.x = __float2half_rn(v0 - __half2float(h0));
        lo01.y = __float2half_rn(v1 - __half2float(h1));
        lo23.x = __float2half_rn(v2 - __half2float(h2));
        lo23.y = __float2half_rn(v3 - __half2float(h3));
        *(__half2*)&g_ah[idx] = hi01;
        *(__half2*)&g_ah[idx + 2] = hi23;
        *(__half2*)&g_al[idx] = lo01;
        *(__half2*)&g_al[idx + 2] = lo23;
    } else {
        outp[idx] = v0; outp[idx + 1] = v1; outp[idx + 2] = v2; outp[idx + 3] = v3;
    }
}

// H=1, C=128 (layer 3): thread t owns channel t, no relu.
__global__ void aggregate1(const float* __restrict__ bias, float* __restrict__ outp) {
    int n = blockIdx.x;
    int t = threadIdx.x;
    __shared__ int   ssrc[128];
    __shared__ float sw[128];

    int beg = g_off[n], end = g_off[n + 1];
    float adh = g_adst[n];
    float acc = 0.f, den = 0.f;

    for (int base = beg; base < end; base += 128) {
        int k = base + t;
        if (k < end) {
            int s = g_esrc[k];
            ssrc[t] = s;
            float e = g_asrc[s] + adh;
            e = e > 0.f ? e : 0.2f * e;
            sw[t] = __expf(e);
        }
        __syncthreads();
        int cnt = min(128, end - base);
#pragma unroll 4
        for (int j = 0; j < cnt; j++) {
            int s = ssrc[j];
            float w = sw[j];
            acc += w * __half2float(g_hh[(size_t)s * 128 + t]);
            den += w;
        }
        __syncthreads();
    }
    outp[(size_t)n * 128 + t] = acc / den + bias[t];
}

// ------------------------- launch ---------------------------------------------
extern "C" void kernel_launch(void* const* d_in, const int* in_sizes, int n_in,
                              void* d_out, int out_size) {
    const float* x   = (const float*)d_in[0];
    const int*   ei  = (const int*)d_in[1];
    const float* W1  = (const float*)d_in[2];
    const float* as1 = (const float*)d_in[3];
    const float* ad1 = (const float*)d_in[4];
    const float* b1  = (const float*)d_in[5];
    const float* W2  = (const float*)d_in[6];
    const float* as2 = (const float*)d_in[7];
    const float* ad2 = (const float*)d_in[8];
    const float* b2  = (const float*)d_in[9];
    const float* W3  = (const float*)d_in[10];
    const float* as3 = (const float*)d_in[11];
    const float* ad3 = (const float*)d_in[12];
    const float* b3  = (const float*)d_in[13];
    float* out = (float*)d_out;

    int N = in_sizes[0] / 256;   // 30000
    int E = in_sizes[1] / 2;     // 480000

    cudaFuncSetAttribute(hgemm, cudaFuncAttributeMaxDynamicSharedMemorySize, SMTOT);

    int MT = (N + 127) / 128;  // 235

    split_fp16<<<(N * 256 + 255) / 256, 256>>>(x, N * 256);            // 0
    wsplit<<<(256 * 512 + 255) / 256, 256>>>(W1, 256, 512);            // 1
    deg_init<<<(N + 255) / 256, 256>>>(N);                             // 2
    hgemm<<<dim3(4, MT), 256, SMTOT>>>(N, 512, 256, as1, ad1, 4);      // 3 <- captured
    deg_count<<<(E + 255) / 256, 256>>>(ei, E, N);                     // 4
    scan1024<<<1, 1024>>>(N);                                          // 5
    fill_csc<<<(E + N + 255) / 256, 256>>>(ei, E, N);                  // 6
    aggregate4<<<N, 128>>>(b1, 1, nullptr);                            // 7

    // ---- layer 2 ----
    wsplit<<<(512 * 512 + 255) / 256, 256>>>(W2, 512, 512);
    hgemm<<<dim3(4, MT), 256, SMTOT>>>(N, 512, 512, as2, ad2, 4);
    aggregate4<<<N, 128>>>(b2, 1, nullptr);

    // ---- layer 3 ----
    wsplit<<<(512 * 128 + 255) / 256, 256>>>(W3, 512, 128);
    hgemm<<<dim3(1, MT), 256, SMTOT>>>(N, 128, 512, as3, ad3, 1);
    aggregate1<<<N, 128>>>(b3, out);
}

// round 16
// speedup vs baseline: 1.5159x; 1.2194x over previous
#include <cuda_runtime.h>
#include <cuda_fp16.h>
#include <math.h>
#include <stdint.h>

#define NMAX 30000
#define EMAX 480000
#define TEMAX (EMAX + NMAX)

// ------------------------- device scratch (static; no allocs) ----------------
__device__ __align__(16) __half g_hh[(size_t)NMAX * 512];   // GEMM output (fp16)
__device__ __align__(16) __half g_ah[(size_t)NMAX * 512];   // activation hi (fp16)
__device__ __align__(16) __half g_al[(size_t)NMAX * 512];   // activation lo (fp16)
__device__ __align__(16) __half g_w[512 * 512];             // W1^T (fp16)
__device__ __align__(16) __half g_w2[512 * 512];            // W2^T (fp16)
__device__ __align__(16) __half g_w3[512 * 128];            // W3^T (fp16)
__device__ __align__(16) float g_asrc[NMAX * 4];
__device__ __align__(16) float g_adst[NMAX * 4];
__device__ int   g_deg[NMAX];
__device__ int   g_off[NMAX + 1];
__device__ int   g_cur[NMAX];
__device__ int   g_esrc[TEMAX];

#define SW128(o) ((o) ^ (((o) >> 3) & 0x70))

__device__ __forceinline__ uint32_t smem_u32(const void* p) {
    uint32_t a;
    asm("{ .reg .u64 t; cvta.to.shared.u64 t, %1; cvt.u32.u64 %0, t; }" : "=r"(a) : "l"(p));
    return a;
}
__device__ __forceinline__ void ldm_x4(uint32_t* r, uint32_t addr) {
    asm volatile("ldmatrix.sync.aligned.m8n8.x4.shared.b16 {%0,%1,%2,%3}, [%4];"
                 : "=r"(r[0]), "=r"(r[1]), "=r"(r[2]), "=r"(r[3]) : "r"(addr));
}
__device__ __forceinline__ void mma16816(float* d, const uint32_t* a, const uint32_t* b) {
    asm volatile(
        "mma.sync.aligned.m16n8k16.row.col.f32.f16.f16.f32 "
        "{%0,%1,%2,%3}, {%4,%5,%6,%7}, {%8,%9}, {%0,%1,%2,%3};"
        : "+f"(d[0]), "+f"(d[1]), "+f"(d[2]), "+f"(d[3])
        : "r"(a[0]), "r"(a[1]), "r"(a[2]), "r"(a[3]), "r"(b[0]), "r"(b[1]));
}
__device__ __forceinline__ void cp_async16(uint32_t saddr, const void* g, int srcBytes) {
    asm volatile("cp.async.cg.shared.global [%0], [%1], 16, %2;"
                 :: "r"(saddr), "l"(g), "r"(srcBytes) : "memory");
}
#define CP_COMMIT() asm volatile("cp.async.commit_group;" ::: "memory")
#define CP_WAIT(n)  asm volatile("cp.async.wait_group %0;" :: "n"(n) : "memory")

// ------------------------- CSC build ----------------------------------------
__global__ void deg_init(int N) {
    int i = blockIdx.x * blockDim.x + threadIdx.x;
    if (i < N) g_deg[i] = 1;
}
__global__ void deg_count(const int* __restrict__ ei, int E, int N) {
    int i = blockIdx.x * blockDim.x + threadIdx.x;
    if (i < E) {
        int d = ei[E + i];
        if (d >= 0 && d < N) atomicAdd(&g_deg[d], 1);
    }
}
__global__ void scan1024(int N) {
    __shared__ int sp[1024];
    int t = threadIdx.x;
    int IT = (N + 1023) >> 10;
    int b = t * IT, e = min(N, b + IT);
    int s = 0;
    for (int i = b; i < e; i++) s += g_deg[i];
    sp[t] = s;
    __syncthreads();
    for (int off = 1; off < 1024; off <<= 1) {
        int v = (t >= off) ? sp[t - off] : 0;
        __syncthreads();
        sp[t] += v;
        __syncthreads();
    }
    int run = (t == 0) ? 0 : sp[t - 1];
    for (int i = b; i < e; i++) { g_off[i] = run; g_cur[i] = run; run += g_deg[i]; }
    if (t == 1023) g_off[N] = sp[1023];
}
__global__ void fill_csc(const int* __restrict__ ei, int E, int N) {
    int i = blockIdx.x * blockDim.x + threadIdx.x;
    if (i >= E + N) return;
    int s, d;
    if (i < E) { s = ei[i]; d = ei[E + i]; }
    else       { s = i - E; d = s; }
    if (s < 0 || s >= N || d < 0 || d >= N) return;
    int pos = atomicAdd(&g_cur[d], 1);
    if (pos >= 0 && pos < TEMAX) g_esrc[pos] = s;
}

// ------------------------- fp16 split (layer-1 input) / weight transpose -----
__global__ void split_fp16(const float* __restrict__ in, int n) {
    int i = blockIdx.x * blockDim.x + threadIdx.x;
    if (i >= n) return;
    float v = in[i];
    __half h = __float2half_rn(v);
    g_ah[i] = h;
    g_al[i] = __float2half_rn(v - __half2float(h));
}
__global__ void wsplit(const float* __restrict__ W, __half* __restrict__ dst,
                       int K, int N) {
    int i = blockIdx.x * blockDim.x + threadIdx.x;
    if (i >= K * N) return;
    int k = i / N, n = i - k * N;
    dst[(size_t)n * K + k] = __float2half_rn(W[i]);
}

// ------------------------- HMMA fp16 2-term GEMM + fused attn ----------------
#define STAGE_B 49152
#define OFF_AH 0
#define OFF_AL 16384
#define OFF_B  32768
#define SMTOT (2 * STAGE_B)

__global__ __launch_bounds__(256, 2) void hgemm(const __half* __restrict__ Wt,
                                                int M, int N, int K,
                                                const float* __restrict__ at_s,
                                                const float* __restrict__ at_d,
                                                int H) {
    extern __shared__ char smem[];
    uint32_t sb = smem_u32(smem);
    int t = threadIdx.x, lane = t & 31, wid = t >> 5;
    int wm = (wid & 3) * 32;
    int wn = (wid >> 2) * 64;
    int row0 = blockIdx.y * 128, col0 = blockIdx.x * 128;
    int hd = blockIdx.x;

    float acc[2][8][4];
#pragma unroll
    for (int i = 0; i < 2; i++)
#pragma unroll
        for (int j = 0; j < 8; j++)
#pragma unroll
            for (int k = 0; k < 4; k++) acc[i][j][k] = 0.f;

    int q = t & 7;
    int rr = t >> 3;
    int nc = K >> 6;

    auto issue = [&](int c) {
        int k0 = c << 6;
        uint32_t stg = sb + (uint32_t)(c & 1) * STAGE_B;
#pragma unroll
        for (int j = 0; j < 4; j++) {
            int r = rr + j * 32;
            uint32_t off = SW128((uint32_t)(r * 128 + q * 16));
            int gr = row0 + r;
            int ok = (gr < M) ? 16 : 0;
            int grc = ok ? gr : 0;
            cp_async16(stg + OFF_AH + off, &g_ah[(size_t)grc * K + k0 + q * 8], ok);
            cp_async16(stg + OFF_AL + off, &g_al[(size_t)grc * K + k0 + q * 8], ok);
            int gn = col0 + r;
            cp_async16(stg + OFF_B + off, &Wt[(size_t)gn * K + k0 + q * 8], 16);
        }
        CP_COMMIT();
    };

    issue(0);

    for (int c = 0; c < nc; c++) {
        if (c + 1 < nc) {
            issue(c + 1);
            CP_WAIT(1);
        } else {
            CP_WAIT(0);
        }
        __syncthreads();
        uint32_t stg = sb + (uint32_t)(c & 1) * STAGE_B;
#pragma unroll
        for (int ks = 0; ks < 4; ks++) {
            int kc = ks * 16;
            uint32_t ah[2][4], al[2][4];
#pragma unroll
            for (int mt = 0; mt < 2; mt++) {
                int r = wm + mt * 16 + (lane & 15);
                uint32_t off = SW128((uint32_t)(r * 128 + (kc + ((lane >> 4) << 3)) * 2));
                ldm_x4(ah[mt], stg + OFF_AH + off);
                ldm_x4(al[mt], stg + OFF_AL + off);
            }
            uint32_t bb[4][4];
#pragma unroll
            for (int p = 0; p < 4; p++) {
                int r = wn + p * 16 + ((lane >> 4) << 3) + (lane & 7);
                uint32_t off = SW128((uint32_t)(r * 128 + (kc + ((lane >> 3) & 1) * 8) * 2));
                ldm_x4(bb[p], stg + OFF_B + off);
            }
#pragma unroll
            for (int mt = 0; mt < 2; mt++)
#pragma unroll
                for (int nt = 0; nt < 8; nt++) {
                    const uint32_t* bp = &bb[nt >> 1][(nt & 1) * 2];
                    mma16816(acc[mt][nt], ah[mt], bp);
                    mma16816(acc[mt][nt], al[mt], bp);
                }
        }
        __syncthreads();
    }

    // ---- epilogue: store h (fp16) ----
    int g = lane >> 2, cc = (lane & 3) * 2;
#pragma unroll
    for (int mt = 0; mt < 2; mt++) {
        int r0a = row0 + wm + mt * 16 + g;
#pragma unroll
        for (int nt = 0; nt < 8; nt++) {
            int c = col0 + wn + nt * 8 + cc;
            if (r0a < M)
                *(__half2*)&g_hh[(size_t)r0a * N + c] =
                    __floats2half2_rn(acc[mt][nt][0], acc[mt][nt][1]);
            if (r0a + 8 < M)
                *(__half2*)&g_hh[(size_t)(r0a + 8) * N + c] =
                    __floats2half2_rn(acc[mt][nt][2], acc[mt][nt][3]);
        }
    }

    // ---- fused attention coefficients for this head ----
    float ps[2][2] = {{0.f, 0.f}, {0.f, 0.f}};
    float pd[2][2] = {{0.f, 0.f}, {0.f, 0.f}};
    const float* asv = at_s + hd * 128;
    const float* adv = at_d + hd * 128;
#pragma unroll
    for (int nt = 0; nt < 8; nt++) {
        int c = wn + nt * 8 + cc;
        float w0s = asv[c], w1s = asv[c + 1];
        float w0d = adv[c], w1d = adv[c + 1];
#pragma unroll
        for (int mt = 0; mt < 2; mt++) {
            ps[mt][0] += acc[mt][nt][0] * w0s + acc[mt][nt][1] * w1s;
            ps[mt][1] += acc[mt][nt][2] * w0s + acc[mt][nt][3] * w1s;
            pd[mt][0] += acc[mt][nt][0] * w0d + acc[mt][nt][1] * w1d;
            pd[mt][1] += acc[mt][nt][2] * w0d + acc[mt][nt][3] * w1d;
        }
    }
#pragma unroll
    for (int o = 1; o < 4; o <<= 1) {
#pragma unroll
        for (int mt = 0; mt < 2; mt++)
#pragma unroll
            for (int hf = 0; hf < 2; hf++) {
                ps[mt][hf] += __shfl_xor_sync(0xffffffffu, ps[mt][hf], o);
                pd[mt][hf] += __shfl_xor_sync(0xffffffffu, pd[mt][hf], o);
            }
    }
    float* sred = (float*)smem;
    __syncthreads();
    if ((lane & 3) == 0) {
#pragma unroll
        for (int mt = 0; mt < 2; mt++)
#pragma unroll
            for (int hf = 0; hf < 2; hf++) {
                int row = wm + mt * 16 + g + hf * 8;
                sred[((wid >> 2) * 128 + row) * 2 + 0] = ps[mt][hf];
                sred[((wid >> 2) * 128 + row) * 2 + 1] = pd[mt][hf];
            }
    }
    __syncthreads();
    if (t < 128) {
        int gr = row0 + t;
        if (gr < M) {
            g_asrc[gr * H + hd] = sred[t * 2 + 0] + sred[(128 + t) * 2 + 0];
            g_adst[gr * H + hd] = sred[t * 2 + 1] + sred[(128 + t) * 2 + 1];
        }
    }
}

// ------------------------- fused softmax + aggregate + fp16 split ------------
__global__ void aggregate4(const float* __restrict__ bias, int doSplit,
                           float* __restrict__ outp) {
    int n = blockIdx.x;
    int t = threadIdx.x;
    int hd = t >> 5;
    __shared__ int   ssrc[128];
    __shared__ float sw[128 * 4];

    int beg = g_off[n], end = g_off[n + 1];

    float4 adh = *(const float4*)&g_adst[n * 4];
    float4 acc = make_float4(0.f, 0.f, 0.f, 0.f);
    float den = 0.f;

    for (int base = beg; base < end; base += 128) {
        int k = base + t;
        if (k < end) {
            int s = g_esrc[k];
            ssrc[t] = s;
            float4 a = *(const float4*)&g_asrc[s * 4];
            float e0 = a.x + adh.x, e1 = a.y + adh.y, e2 = a.z + adh.z, e3 = a.w + adh.w;
            e0 = e0 > 0.f ? e0 : 0.2f * e0;
            e1 = e1 > 0.f ? e1 : 0.2f * e1;
            e2 = e2 > 0.f ? e2 : 0.2f * e2;
            e3 = e3 > 0.f ? e3 : 0.2f * e3;
            *(float4*)&sw[t * 4] = make_float4(__expf(e0), __expf(e1), __expf(e2), __expf(e3));
        }
        __syncthreads();
        int cnt = min(128, end - base);
        const __half* hbase = g_hh + t * 4;
#pragma unroll 8
        for (int j = 0; j < cnt; j++) {
            int s = ssrc[j];
            float w = sw[j * 4 + hd];
            uint2 hv = *(const uint2*)(hbase + (size_t)s * 512);
            float2 f01 = __half22float2(*(__half2*)&hv.x);
            float2 f23 = __half22float2(*(__half2*)&hv.y);
            acc.x += w * f01.x;
            acc.y += w * f01.y;
            acc.z += w * f23.x;
            acc.w += w * f23.y;
            den += w;
        }
        __syncthreads();
    }

    float inv = 1.f / den;
    float4 b4 = *(const float4*)&bias[t * 4];
    float v0 = fmaxf(acc.x * inv + b4.x, 0.f);
    float v1 = fmaxf(acc.y * inv + b4.y, 0.f);
    float v2 = fmaxf(acc.z * inv + b4.z, 0.f);
    float v3 = fmaxf(acc.w * inv + b4.w, 0.f);
    size_t idx = (size_t)n * 512 + t * 4;
    if (doSplit) {
        __half h0 = __float2half_rn(v0), h1 = __float2half_rn(v1);
        __half h2 = __float2half_rn(v2), h3 = __float2half_rn(v3);
        __half2 hi01, hi23, lo01, lo23;
        hi01.x = h0; hi01.y = h1; hi23.x = h2; hi23.y = h3;
        lo01.x = __float2half_rn(v0 - __half2float(h0));
        lo01.y = __float2half_rn(v1 - __half2float(h1));
        lo23.x = __float2half_rn(v2 - __half2float(h2));
        lo23.y = __float2half_rn(v3 - __half2float(h3));
        *(__half2*)&g_ah[idx] = hi01;
        *(__half2*)&g_ah[idx + 2] = hi23;
        *(__half2*)&g_al[idx] = lo01;
        *(__half2*)&g_al[idx + 2] = lo23;
    } else {
        outp[idx] = v0; outp[idx + 1] = v1; outp[idx + 2] = v2; outp[idx + 3] = v3;
    }
}

__global__ void aggregate1(const float* __restrict__ bias, float* __restrict__ outp) {
    int n = blockIdx.x;
    int t = threadIdx.x;
    __shared__ int   ssrc[128];
    __shared__ float sw[128];

    int beg = g_off[n], end = g_off[n + 1];
    float adh = g_adst[n];
    float acc = 0.f, den = 0.f;

    for (int base = beg; base < end; base += 128) {
        int k = base + t;
        if (k < end) {
            int s = g_esrc[k];
            ssrc[t] = s;
            float e = g_asrc[s] + adh;
            e = e > 0.f ? e : 0.2f * e;
            sw[t] = __expf(e);
        }
        __syncthreads();
        int cnt = min(128, end - base);
#pragma unroll 8
        for (int j = 0; j < cnt; j++) {
            int s = ssrc[j];
            float w = sw[j];
            acc += w * __half2float(g_hh[(size_t)s * 128 + t]);
            den += w;
        }
        __syncthreads();
    }
    outp[(size_t)n * 128 + t] = acc / den + bias[t];
}

// ------------------------- launch ---------------------------------------------
extern "C" void kernel_launch(void* const* d_in, const int* in_sizes, int n_in,
                              void* d_out, int out_size) {
    const float* x   = (const float*)d_in[0];
    const int*   ei  = (const int*)d_in[1];
    const float* W1  = (const float*)d_in[2];
    const float* as1 = (const float*)d_in[3];
    const float* ad1 = (const float*)d_in[4];
    const float* b1  = (const float*)d_in[5];
    const float* W2  = (const float*)d_in[6];
    const float* as2 = (const float*)d_in[7];
    const float* ad2 = (const float*)d_in[8];
    const float* b2  = (const float*)d_in[9];
    const float* W3  = (const float*)d_in[10];
    const float* as3 = (const float*)d_in[11];
    const float* ad3 = (const float*)d_in[12];
    const float* b3  = (const float*)d_in[13];
    float* out = (float*)d_out;

    int N = in_sizes[0] / 256;   // 30000
    int E = in_sizes[1] / 2;     // 480000

    static cudaStream_t s2 = nullptr;
    static cudaEvent_t evFork = nullptr, evJoin = nullptr;
    if (!s2) {
        cudaStreamCreateWithFlags(&s2, cudaStreamNonBlocking);
        cudaEventCreateWithFlags(&evFork, cudaEventDisableTiming);
        cudaEventCreateWithFlags(&evJoin, cudaEventDisableTiming);
        cudaFuncSetAttribute(hgemm, cudaFuncAttributeMaxDynamicSharedMemorySize, SMTOT);
    }

    int MT = (N + 127) / 128;  // 235

    __half *pw1, *pw2, *pw3;
    cudaGetSymbolAddress((void**)&pw1, g_w);    // host-side symbol lookup (used R3+; fine)
    cudaGetSymbolAddress((void**)&pw2, g_w2);
    cudaGetSymbolAddress((void**)&pw3, g_w3);

    // ---- fork: CSC build + W2/W3 transposes on s2 ----
    cudaEventRecord(evFork, 0);
    cudaStreamWaitEvent(s2, evFork, 0);
    deg_init<<<(N + 255) / 256, 256, 0, s2>>>(N);
    deg_count<<<(E + 255) / 256, 256, 0, s2>>>(ei, E, N);
    scan1024<<<1, 1024, 0, s2>>>(N);
    fill_csc<<<(E + N + 255) / 256, 256, 0, s2>>>(ei, E, N);
    wsplit<<<(512 * 512 + 255) / 256, 256, 0, s2>>>(W2, pw2, 512, 512);
    wsplit<<<(512 * 128 + 255) / 256, 256, 0, s2>>>(W3, pw3, 512, 128);
    cudaEventRecord(evJoin, s2);

    // ---- main chain: layer 1 GEMM path ----
    split_fp16<<<(N * 256 + 255) / 256, 256>>>(x, N * 256);
    wsplit<<<(256 * 512 + 255) / 256, 256>>>(W1, pw1, 256, 512);
    hgemm<<<dim3(4, MT), 256, SMTOT>>>(pw1, N, 512, 256, as1, ad1, 4);

    // ---- join, then aggregate + layers 2/3 ----
    cudaStreamWaitEvent(0, evJoin, 0);
    aggregate4<<<N, 128>>>(b1, 1, nullptr);

    hgemm<<<dim3(4, MT), 256, SMTOT>>>(pw2, N, 512, 512, as2, ad2, 4);
    aggregate4<<<N, 128>>>(b2, 1, nullptr);

    hgemm<<<dim3(1, MT), 256, SMTOT>>>(pw3, N, 128, 512, as3, ad3, 1);
    aggregate1<<<N, 128>>>(b3, out);
}